// round 5
// baseline (speedup 1.0000x reference)
#include <cuda_runtime.h>
#include <cstdint>

#define NN 100000
#define NE 3200000
#define NG 64

// Scratch (device globals: no allocation allowed in kernel_launch).
// Stored as int bit-patterns of nonnegative floats so signed-int atomicMax
// == float max (init 0 == 0.0f == the seg_max0+relu identity element).
__device__ int d_h1[NN * 32];
__device__ int d_h2[NN * 32];
__device__ int d_pool[NG * 32];
__device__ int g_is64;   // 1 if index buffers are int64, 0 if int32

// ---------------- packed f32x2 helpers (sm_100+ PTX) ----------------
__device__ __forceinline__ unsigned long long dup2(float x) {
    unsigned long long r;
    asm("mov.b64 %0, {%1, %1};" : "=l"(r) : "f"(x));
    return r;
}
__device__ __forceinline__ unsigned long long pack2(float lo, float hi) {
    unsigned long long r;
    asm("mov.b64 %0, {%1, %2};" : "=l"(r) : "f"(lo), "f"(hi));
    return r;
}
__device__ __forceinline__ void unpack2(unsigned long long v, float& lo, float& hi) {
    asm("mov.b64 {%0, %1}, %2;" : "=f"(lo), "=f"(hi) : "l"(v));
}
__device__ __forceinline__ unsigned long long fma2(
    unsigned long long a, unsigned long long b, unsigned long long c) {
    unsigned long long d;
    asm("fma.rn.f32x2 %0, %1, %2, %3;" : "=l"(d) : "l"(a), "l"(b), "l"(c));
    return d;
}

__device__ __forceinline__ void atomic_max_pos(int* addr, float v) {
    // accumulator is always >= 0 (init 0); nonneg float order == signed int order
    if (v > 0.0f) atomicMax(addr, __float_as_int(v));
}

// Uniform-branch index fetch honoring detected dtype.
__device__ __forceinline__ void load_edge(const void* ei, int e, int& src, int& dst) {
    if (g_is64) {
        const long long* p = (const long long*)ei;
        src = (int)p[e];
        dst = (int)p[NE + e];
    } else {
        const int* p = (const int*)ei;
        src = p[e];
        dst = p[NE + e];
    }
}
__device__ __forceinline__ int load_batch(const void* b, int n) {
    if (g_is64) return (int)((const long long*)b)[n];
    return ((const int*)b)[n];
}

// ---------------- dtype probe ----------------
// int64 buffer of values in [0, 1e5) viewed as int32: odd words are all 0.
// Genuine int32 edge list: odd words are random node ids (all-zero prob ~0).
__global__ void detect_kernel(const int* __restrict__ ei32) {
    if (threadIdx.x == 0 && blockIdx.x == 0) {
        int all0 = 1;
#pragma unroll
        for (int i = 1; i < 64; i += 2)
            if (ei32[i] != 0) all0 = 0;
        g_is64 = all0;
    }
}

// ---------------- zero-init ----------------
__global__ void zero_kernel() {
    int i = blockIdx.x * blockDim.x + threadIdx.x;
    if (i < NN * 32) { d_h1[i] = 0; d_h2[i] = 0; }
    if (i < NG * 32) d_pool[i] = 0;
}

// ---------------- layer 1: pos(4) -> 32 -> 32, seg-max into d_h1 ----------------
__global__ void __launch_bounds__(256) layer1_kernel(
    const float* __restrict__ pos,
    const float* __restrict__ w1a, const float* __restrict__ b1a,
    const float* __restrict__ w1b, const float* __restrict__ b1b,
    const void* __restrict__ ei)
{
    __shared__ __align__(16) float s_wa[4 * 32];   // [j][k] row-major (k-pairs contiguous)
    __shared__ __align__(16) float s_ba[32];
    __shared__ __align__(16) float s_wbT[32 * 32]; // transposed: [c][k] (k-pairs contiguous)
    __shared__ __align__(16) float s_bb[32];

    for (int i = threadIdx.x; i < 128; i += 256) s_wa[i] = w1a[i];
    if (threadIdx.x < 32) { s_ba[threadIdx.x] = b1a[threadIdx.x]; s_bb[threadIdx.x] = b1b[threadIdx.x]; }
    for (int i = threadIdx.x; i < 1024; i += 256) {
        int k = i >> 5, c = i & 31;
        s_wbT[c * 32 + k] = w1b[i];
    }
    __syncthreads();

    int e = blockIdx.x * 256 + threadIdx.x;   // NE % 256 == 0
    int src, dst;
    load_edge(ei, e, src, dst);

    float2 pj = __ldg((const float2*)pos + src);
    float2 pi = __ldg((const float2*)pos + dst);
    float xs[4];
    xs[0] = pj.x; xs[1] = pj.y; xs[2] = pj.x - pi.x; xs[3] = pj.y - pi.y;

    // hidden = relu(x @ w1a + b1a), packed across output pairs
    unsigned long long acc[16];
#pragma unroll
    for (int k2 = 0; k2 < 16; k2++)
        acc[k2] = *(const unsigned long long*)&s_ba[2 * k2];
#pragma unroll
    for (int j = 0; j < 4; j++) {
        unsigned long long xd = dup2(xs[j]);
#pragma unroll
        for (int k2 = 0; k2 < 16; k2++)
            acc[k2] = fma2(xd, *(const unsigned long long*)&s_wa[j * 32 + 2 * k2], acc[k2]);
    }
    unsigned long long hid2[16];
#pragma unroll
    for (int k2 = 0; k2 < 16; k2++) {
        float lo, hi; unpack2(acc[k2], lo, hi);
        hid2[k2] = pack2(fmaxf(lo, 0.0f), fmaxf(hi, 0.0f));
    }

    // m = hidden @ w1b + b1b; atomic seg-max(relu) into d_h1[dst]
    int* outp = d_h1 + dst * 32;
#pragma unroll
    for (int c = 0; c < 32; c++) {
        unsigned long long a2 = 0ull; // (0.0f, 0.0f)
        const unsigned long long* wrow = (const unsigned long long*)&s_wbT[c * 32];
#pragma unroll
        for (int k2 = 0; k2 < 16; k2++)
            a2 = fma2(hid2[k2], wrow[k2], a2);
        float lo, hi; unpack2(a2, lo, hi);
        atomic_max_pos(&outp[c], lo + hi + s_bb[c]);
    }
}

// ---------------- layer 2: [h1(32), dpos(2)] -> 32 -> 32, seg-max into d_h2 ----------------
__global__ void __launch_bounds__(256) layer2_kernel(
    const float* __restrict__ pos,
    const float* __restrict__ w2a, const float* __restrict__ b2a,
    const float* __restrict__ w2b, const float* __restrict__ b2b,
    const void* __restrict__ ei)
{
    __shared__ __align__(16) float s_wa[34 * 32];
    __shared__ __align__(16) float s_ba[32];
    __shared__ __align__(16) float s_wbT[32 * 32];
    __shared__ __align__(16) float s_bb[32];

    for (int i = threadIdx.x; i < 34 * 32; i += 256) s_wa[i] = w2a[i];
    if (threadIdx.x < 32) { s_ba[threadIdx.x] = b2a[threadIdx.x]; s_bb[threadIdx.x] = b2b[threadIdx.x]; }
    for (int i = threadIdx.x; i < 1024; i += 256) {
        int k = i >> 5, c = i & 31;
        s_wbT[c * 32 + k] = w2b[i];
    }
    __syncthreads();

    int e = blockIdx.x * 256 + threadIdx.x;
    int src, dst;
    load_edge(ei, e, src, dst);

    float2 pj = __ldg((const float2*)pos + src);
    float2 pi = __ldg((const float2*)pos + dst);

    float xs[34];
    const float4* hp = (const float4*)(const void*)(d_h1 + src * 32);
#pragma unroll
    for (int q = 0; q < 8; q++) {
        float4 v = hp[q];
        xs[4 * q + 0] = v.x; xs[4 * q + 1] = v.y;
        xs[4 * q + 2] = v.z; xs[4 * q + 3] = v.w;
    }
    xs[32] = pj.x - pi.x;
    xs[33] = pj.y - pi.y;

    unsigned long long acc[16];
#pragma unroll
    for (int k2 = 0; k2 < 16; k2++)
        acc[k2] = *(const unsigned long long*)&s_ba[2 * k2];
#pragma unroll
    for (int j = 0; j < 34; j++) {
        unsigned long long xd = dup2(xs[j]);
#pragma unroll
        for (int k2 = 0; k2 < 16; k2++)
            acc[k2] = fma2(xd, *(const unsigned long long*)&s_wa[j * 32 + 2 * k2], acc[k2]);
    }
    unsigned long long hid2[16];
#pragma unroll
    for (int k2 = 0; k2 < 16; k2++) {
        float lo, hi; unpack2(acc[k2], lo, hi);
        hid2[k2] = pack2(fmaxf(lo, 0.0f), fmaxf(hi, 0.0f));
    }

    int* outp = d_h2 + dst * 32;
#pragma unroll
    for (int c = 0; c < 32; c++) {
        unsigned long long a2 = 0ull;
        const unsigned long long* wrow = (const unsigned long long*)&s_wbT[c * 32];
#pragma unroll
        for (int k2 = 0; k2 < 16; k2++)
            a2 = fma2(hid2[k2], wrow[k2], a2);
        float lo, hi; unpack2(a2, lo, hi);
        atomic_max_pos(&outp[c], lo + hi + s_bb[c]);
    }
}

// ---------------- global max pool per graph (batch is sorted) ----------------
#define RLEN 128
#define NRANGES ((NN + RLEN - 1) / RLEN)   // 782
#define POOL_THREADS (NRANGES * 32)        // 25024

__global__ void pool_kernel(const void* __restrict__ batch) {
    int t = blockIdx.x * blockDim.x + threadIdx.x;
    if (t >= POOL_THREADS) return;
    int r = t >> 5;        // node range (warp-uniform)
    int c = t & 31;        // channel (lane)
    int n0 = r * RLEN;
    int n1 = min(n0 + RLEN, NN);

    int curg = load_batch(batch, n0);
    float curm = 0.0f;
    for (int n = n0; n < n1; n++) {
        int b = load_batch(batch, n);
        float v = __int_as_float(d_h2[n * 32 + c]);   // >= 0
        if (b != curg) {
            if (curm > 0.0f) atomicMax(&d_pool[curg * 32 + c], __float_as_int(curm));
            curg = b;
            curm = v;
        } else {
            curm = fmaxf(curm, v);
        }
    }
    if (curm > 0.0f) atomicMax(&d_pool[curg * 32 + c], __float_as_int(curm));
}

// ---------------- classifier: out[g] = pool[g] @ wc + bc ----------------
__global__ void final_kernel(const float* __restrict__ wc,
                             const float* __restrict__ bc,
                             float* __restrict__ out) {
    int t = threadIdx.x;
    if (t >= NG * 3) return;
    int g = t / 3, o = t % 3;
    float acc = bc[o];
#pragma unroll
    for (int cc = 0; cc < 32; cc++)
        acc += __int_as_float(d_pool[g * 32 + cc]) * wc[cc * 3 + o];
    out[t] = acc;
}

// ---------------- launch ----------------
extern "C" void kernel_launch(void* const* d_in, const int* in_sizes, int n_in,
                              void* d_out, int out_size) {
    const float* pos = (const float*)d_in[0];
    const float* w1a = (const float*)d_in[1];
    const float* b1a = (const float*)d_in[2];
    const float* w1b = (const float*)d_in[3];
    const float* b1b = (const float*)d_in[4];
    const float* w2a = (const float*)d_in[5];
    const float* b2a = (const float*)d_in[6];
    const float* w2b = (const float*)d_in[7];
    const float* b2b = (const float*)d_in[8];
    const float* wc  = (const float*)d_in[9];
    const float* bc  = (const float*)d_in[10];
    const void* ei    = d_in[11];
    const void* batch = d_in[12];

    detect_kernel<<<1, 32>>>((const int*)ei);
    zero_kernel<<<(NN * 32 + 255) / 256, 256>>>();
    layer1_kernel<<<NE / 256, 256>>>(pos, w1a, b1a, w1b, b1b, ei);
    layer2_kernel<<<NE / 256, 256>>>(pos, w2a, b2a, w2b, b2b, ei);
    pool_kernel<<<(POOL_THREADS + 255) / 256, 256>>>(batch);
    final_kernel<<<1, 192>>>(wc, bc, (float*)d_out);
}

// round 9
// speedup vs baseline: 1.0252x; 1.0252x over previous
#include <cuda_runtime.h>
#include <cstdint>

#define NN 100000
#define NE 3200000
#define NG 64

// Scratch (device globals). Values stored as int bit-patterns of nonnegative
// floats so signed-int atomicMax == float max (0 == 0.0f == identity of
// seg_max0+relu).
__device__ int d_h1[NN * 32];
__device__ int d_h2[NN * 32];
__device__ int d_pool[NG * 32];
__device__ int g_is64;   // 1 if index buffers are int64, 0 if int32

// ---------------- packed f32x2 helpers (sm_100+ PTX) ----------------
__device__ __forceinline__ unsigned long long dup2(float x) {
    unsigned long long r;
    asm("mov.b64 %0, {%1, %1};" : "=l"(r) : "f"(x));
    return r;
}
__device__ __forceinline__ unsigned long long pack2(float lo, float hi) {
    unsigned long long r;
    asm("mov.b64 %0, {%1, %2};" : "=l"(r) : "f"(lo), "f"(hi));
    return r;
}
__device__ __forceinline__ void unpack2(unsigned long long v, float& lo, float& hi) {
    asm("mov.b64 {%0, %1}, %2;" : "=f"(lo), "=f"(hi) : "l"(v));
}
__device__ __forceinline__ unsigned long long fma2(
    unsigned long long a, unsigned long long b, unsigned long long c) {
    unsigned long long d;
    asm("fma.rn.f32x2 %0, %1, %2, %3;" : "=l"(d) : "l"(a), "l"(b), "l"(c));
    return d;
}

// Uniform-branch index fetch honoring detected dtype.
__device__ __forceinline__ void load_edge(const void* ei, int e, int& src, int& dst) {
    if (g_is64) {
        const long long* p = (const long long*)ei;
        src = (int)p[e];
        dst = (int)p[NE + e];
    } else {
        const int* p = (const int*)ei;
        src = p[e];
        dst = p[NE + e];
    }
}
__device__ __forceinline__ int load_batch(const void* b, int n) {
    if (g_is64) return (int)((const long long*)b)[n];
    return ((const int*)b)[n];
}

// ---------------- dtype probe ----------------
// int64 buffer of values in [0, 1e5) viewed as int32: odd words are all 0.
__global__ void detect_kernel(const int* __restrict__ ei32) {
    if (threadIdx.x == 0 && blockIdx.x == 0) {
        int all0 = 1;
#pragma unroll
        for (int i = 1; i < 64; i += 2)
            if (ei32[i] != 0) all0 = 0;
        g_is64 = all0;
    }
}

// ---------------- zero-init ----------------
__global__ void zero_kernel() {
    int i = blockIdx.x * blockDim.x + threadIdx.x;
    if (i < NN * 32) { d_h1[i] = 0; d_h2[i] = 0; }
    if (i < NG * 32) d_pool[i] = 0;
}

// ---------------- layer 1: pos(4) -> 32 -> 32, seg-max into d_h1 ----------------
__global__ void __launch_bounds__(256) layer1_kernel(
    const float* __restrict__ pos,
    const float* __restrict__ w1a, const float* __restrict__ b1a,
    const float* __restrict__ w1b, const float* __restrict__ b1b,
    const void* __restrict__ ei)
{
    __shared__ __align__(16) float s_wa[4 * 32];   // [j][k] (k-pairs contiguous)
    __shared__ __align__(16) float s_ba[32];
    __shared__ __align__(16) float s_wbT[32 * 32]; // transposed: [c][k]
    __shared__ __align__(16) float s_bb[32];

    for (int i = threadIdx.x; i < 128; i += 256) s_wa[i] = w1a[i];
    if (threadIdx.x < 32) { s_ba[threadIdx.x] = b1a[threadIdx.x]; s_bb[threadIdx.x] = b1b[threadIdx.x]; }
    for (int i = threadIdx.x; i < 1024; i += 256) {
        int k = i >> 5, c = i & 31;
        s_wbT[c * 32 + k] = w1b[i];
    }
    __syncthreads();

    int e = blockIdx.x * 256 + threadIdx.x;   // NE % 256 == 0
    int src, dst;
    load_edge(ei, e, src, dst);

    // Prefetch current dst accumulator values early (latency hides under MLP).
    int* outp = d_h1 + dst * 32;
    int4 cur[8];
    {
        const int4* cp = (const int4*)(const void*)outp;
#pragma unroll
        for (int q = 0; q < 8; q++) cur[q] = cp[q];
    }

    float2 pj = __ldg((const float2*)pos + src);
    float2 pi = __ldg((const float2*)pos + dst);
    float xs[4];
    xs[0] = pj.x; xs[1] = pj.y; xs[2] = pj.x - pi.x; xs[3] = pj.y - pi.y;

    // hidden = relu(x @ w1a + b1a), packed across output pairs
    unsigned long long acc[16];
    {
        const ulonglong2* bp = (const ulonglong2*)s_ba;
#pragma unroll
        for (int q = 0; q < 8; q++) { ulonglong2 b2 = bp[q]; acc[2*q] = b2.x; acc[2*q+1] = b2.y; }
    }
#pragma unroll
    for (int j = 0; j < 4; j++) {
        unsigned long long xd = dup2(xs[j]);
        const ulonglong2* wp = (const ulonglong2*)&s_wa[j * 32];
#pragma unroll
        for (int q = 0; q < 8; q++) {
            ulonglong2 w = wp[q];                      // LDS.128
            acc[2*q]   = fma2(xd, w.x, acc[2*q]);
            acc[2*q+1] = fma2(xd, w.y, acc[2*q+1]);
        }
    }
    unsigned long long hid2[16];
#pragma unroll
    for (int k2 = 0; k2 < 16; k2++) {
        float lo, hi; unpack2(acc[k2], lo, hi);
        hid2[k2] = pack2(fmaxf(lo, 0.0f), fmaxf(hi, 0.0f));
    }

    // m = hidden @ w1b + b1b; conditional atomic seg-max into d_h1[dst]
    const int* curw = (const int*)cur;
#pragma unroll
    for (int c = 0; c < 32; c++) {
        unsigned long long a2 = 0ull;
        const ulonglong2* wr = (const ulonglong2*)&s_wbT[c * 32];
#pragma unroll
        for (int q = 0; q < 8; q++) {
            ulonglong2 w = wr[q];                      // LDS.128
            a2 = fma2(hid2[2*q],   w.x, a2);
            a2 = fma2(hid2[2*q+1], w.y, a2);
        }
        float lo, hi; unpack2(a2, lo, hi);
        float v = lo + hi + s_bb[c];
        // cur >= 0 always; monotone max => stale read is safe to compare against
        if (v > __int_as_float(curw[c]))
            atomicMax(&outp[c], __float_as_int(v));
    }
}

// ---------------- layer 2: [h1(32), dpos(2)] -> 32 -> 32, seg-max into d_h2 ----------------
__global__ void __launch_bounds__(256) layer2_kernel(
    const float* __restrict__ pos,
    const float* __restrict__ w2a, const float* __restrict__ b2a,
    const float* __restrict__ w2b, const float* __restrict__ b2b,
    const void* __restrict__ ei)
{
    __shared__ __align__(16) float s_wa[34 * 32];
    __shared__ __align__(16) float s_ba[32];
    __shared__ __align__(16) float s_wbT[32 * 32];
    __shared__ __align__(16) float s_bb[32];

    for (int i = threadIdx.x; i < 34 * 32; i += 256) s_wa[i] = w2a[i];
    if (threadIdx.x < 32) { s_ba[threadIdx.x] = b2a[threadIdx.x]; s_bb[threadIdx.x] = b2b[threadIdx.x]; }
    for (int i = threadIdx.x; i < 1024; i += 256) {
        int k = i >> 5, c = i & 31;
        s_wbT[c * 32 + k] = w2b[i];
    }
    __syncthreads();

    int e = blockIdx.x * 256 + threadIdx.x;
    int src, dst;
    load_edge(ei, e, src, dst);

    // Prefetch current dst accumulator values early.
    int* outp = d_h2 + dst * 32;
    int4 cur[8];
    {
        const int4* cp = (const int4*)(const void*)outp;
#pragma unroll
        for (int q = 0; q < 8; q++) cur[q] = cp[q];
    }

    float2 pj = __ldg((const float2*)pos + src);
    float2 pi = __ldg((const float2*)pos + dst);

    float xs[34];
    const float4* hp = (const float4*)(const void*)(d_h1 + src * 32);
#pragma unroll
    for (int q = 0; q < 8; q++) {
        float4 v = hp[q];
        xs[4 * q + 0] = v.x; xs[4 * q + 1] = v.y;
        xs[4 * q + 2] = v.z; xs[4 * q + 3] = v.w;
    }
    xs[32] = pj.x - pi.x;
    xs[33] = pj.y - pi.y;

    unsigned long long acc[16];
    {
        const ulonglong2* bp = (const ulonglong2*)s_ba;
#pragma unroll
        for (int q = 0; q < 8; q++) { ulonglong2 b2 = bp[q]; acc[2*q] = b2.x; acc[2*q+1] = b2.y; }
    }
#pragma unroll
    for (int j = 0; j < 34; j++) {
        unsigned long long xd = dup2(xs[j]);
        const ulonglong2* wp = (const ulonglong2*)&s_wa[j * 32];
#pragma unroll
        for (int q = 0; q < 8; q++) {
            ulonglong2 w = wp[q];                      // LDS.128
            acc[2*q]   = fma2(xd, w.x, acc[2*q]);
            acc[2*q+1] = fma2(xd, w.y, acc[2*q+1]);
        }
    }
    unsigned long long hid2[16];
#pragma unroll
    for (int k2 = 0; k2 < 16; k2++) {
        float lo, hi; unpack2(acc[k2], lo, hi);
        hid2[k2] = pack2(fmaxf(lo, 0.0f), fmaxf(hi, 0.0f));
    }

    const int* curw = (const int*)cur;
#pragma unroll
    for (int c = 0; c < 32; c++) {
        unsigned long long a2 = 0ull;
        const ulonglong2* wr = (const ulonglong2*)&s_wbT[c * 32];
#pragma unroll
        for (int q = 0; q < 8; q++) {
            ulonglong2 w = wr[q];                      // LDS.128
            a2 = fma2(hid2[2*q],   w.x, a2);
            a2 = fma2(hid2[2*q+1], w.y, a2);
        }
        float lo, hi; unpack2(a2, lo, hi);
        float v = lo + hi + s_bb[c];
        if (v > __int_as_float(curw[c]))
            atomicMax(&outp[c], __float_as_int(v));
    }
}

// ---------------- global max pool per graph (batch is sorted) ----------------
#define RLEN 128
#define NRANGES ((NN + RLEN - 1) / RLEN)   // 782
#define POOL_THREADS (NRANGES * 32)        // 25024

__global__ void pool_kernel(const void* __restrict__ batch) {
    int t = blockIdx.x * blockDim.x + threadIdx.x;
    if (t >= POOL_THREADS) return;
    int r = t >> 5;        // node range (warp-uniform)
    int c = t & 31;        // channel (lane)
    int n0 = r * RLEN;
    int n1 = min(n0 + RLEN, NN);

    int curg = load_batch(batch, n0);
    float curm = 0.0f;
    for (int n = n0; n < n1; n++) {
        int b = load_batch(batch, n);
        float v = __int_as_float(d_h2[n * 32 + c]);   // >= 0
        if (b != curg) {
            if (curm > 0.0f) atomicMax(&d_pool[curg * 32 + c], __float_as_int(curm));
            curg = b;
            curm = v;
        } else {
            curm = fmaxf(curm, v);
        }
    }
    if (curm > 0.0f) atomicMax(&d_pool[curg * 32 + c], __float_as_int(curm));
}

// ---------------- classifier: out[g] = pool[g] @ wc + bc ----------------
__global__ void final_kernel(const float* __restrict__ wc,
                             const float* __restrict__ bc,
                             float* __restrict__ out) {
    int t = threadIdx.x;
    if (t >= NG * 3) return;
    int g = t / 3, o = t % 3;
    float acc = bc[o];
#pragma unroll
    for (int cc = 0; cc < 32; cc++)
        acc += __int_as_float(d_pool[g * 32 + cc]) * wc[cc * 3 + o];
    out[t] = acc;
}

// ---------------- launch ----------------
extern "C" void kernel_launch(void* const* d_in, const int* in_sizes, int n_in,
                              void* d_out, int out_size) {
    const float* pos = (const float*)d_in[0];
    const float* w1a = (const float*)d_in[1];
    const float* b1a = (const float*)d_in[2];
    const float* w1b = (const float*)d_in[3];
    const float* b1b = (const float*)d_in[4];
    const float* w2a = (const float*)d_in[5];
    const float* b2a = (const float*)d_in[6];
    const float* w2b = (const float*)d_in[7];
    const float* b2b = (const float*)d_in[8];
    const float* wc  = (const float*)d_in[9];
    const float* bc  = (const float*)d_in[10];
    const void* ei    = d_in[11];
    const void* batch = d_in[12];

    detect_kernel<<<1, 32>>>((const int*)ei);
    zero_kernel<<<(NN * 32 + 255) / 256, 256>>>();
    layer1_kernel<<<NE / 256, 256>>>(pos, w1a, b1a, w1b, b1b, ei);
    layer2_kernel<<<NE / 256, 256>>>(pos, w2a, b2a, w2b, b2b, ei);
    pool_kernel<<<(POOL_THREADS + 255) / 256, 256>>>(batch);
    final_kernel<<<1, 192>>>(wc, bc, (float*)d_out);
}

// round 11
// speedup vs baseline: 1.0257x; 1.0004x over previous
#include <cuda_runtime.h>
#include <cstdint>

#define NN 100000
#define NE 3200000
#define NG 64

// Scratch (device globals). Values stored as int bit-patterns of nonnegative
// floats so signed-int atomicMax == float max (0 == 0.0f == identity of
// seg_max0+relu).
__device__ int d_h1[NN * 32];
__device__ int d_h2[NN * 32];
__device__ int d_pool[NG * 32];
__device__ int g_is64;   // 1 if index buffers are int64, 0 if int32

// ---------------- packed f32x2 helpers (sm_100+ PTX) ----------------
__device__ __forceinline__ unsigned long long dup2(float x) {
    unsigned long long r;
    asm("mov.b64 %0, {%1, %1};" : "=l"(r) : "f"(x));
    return r;
}
__device__ __forceinline__ unsigned long long pack2(float lo, float hi) {
    unsigned long long r;
    asm("mov.b64 %0, {%1, %2};" : "=l"(r) : "f"(lo), "f"(hi));
    return r;
}
__device__ __forceinline__ void unpack2(unsigned long long v, float& lo, float& hi) {
    asm("mov.b64 {%0, %1}, %2;" : "=f"(lo), "=f"(hi) : "l"(v));
}
__device__ __forceinline__ unsigned long long fma2(
    unsigned long long a, unsigned long long b, unsigned long long c) {
    unsigned long long d;
    asm("fma.rn.f32x2 %0, %1, %2, %3;" : "=l"(d) : "l"(a), "l"(b), "l"(c));
    return d;
}

// Uniform-branch index fetch honoring detected dtype.
__device__ __forceinline__ void load_edge(const void* ei, int e, int& src, int& dst) {
    if (g_is64) {
        const long long* p = (const long long*)ei;
        src = (int)p[e];
        dst = (int)p[NE + e];
    } else {
        const int* p = (const int*)ei;
        src = p[e];
        dst = p[NE + e];
    }
}
__device__ __forceinline__ int load_batch(const void* b, int n) {
    if (g_is64) return (int)((const long long*)b)[n];
    return ((const int*)b)[n];
}

// ---------------- dtype probe ----------------
// int64 buffer of values in [0, 1e5) viewed as int32: odd words are all 0.
__global__ void detect_kernel(const int* __restrict__ ei32) {
    if (threadIdx.x == 0 && blockIdx.x == 0) {
        int all0 = 1;
#pragma unroll
        for (int i = 1; i < 64; i += 2)
            if (ei32[i] != 0) all0 = 0;
        g_is64 = all0;
    }
}

// ---------------- zero-init ----------------
__global__ void zero_kernel() {
    int i = blockIdx.x * blockDim.x + threadIdx.x;
    if (i < NN * 32) { d_h1[i] = 0; d_h2[i] = 0; }
    if (i < NG * 32) d_pool[i] = 0;
}

// ---------------- layer 1: pos(4) -> 32 -> 32, seg-max into d_h1 ----------------
__global__ void __launch_bounds__(256) layer1_kernel(
    const float* __restrict__ pos,
    const float* __restrict__ w1a, const float* __restrict__ b1a,
    const float* __restrict__ w1b, const float* __restrict__ b1b,
    const void* __restrict__ ei)
{
    __shared__ __align__(16) float s_wa[4 * 32];   // [j][k] (k-pairs contiguous)
    __shared__ __align__(16) float s_ba[32];
    __shared__ __align__(16) float s_wbT[32 * 32]; // transposed: [c][k]
    __shared__ __align__(16) float s_bb[32];

    for (int i = threadIdx.x; i < 128; i += 256) s_wa[i] = w1a[i];
    if (threadIdx.x < 32) { s_ba[threadIdx.x] = b1a[threadIdx.x]; s_bb[threadIdx.x] = b1b[threadIdx.x]; }
    for (int i = threadIdx.x; i < 1024; i += 256) {
        int k = i >> 5, c = i & 31;
        s_wbT[c * 32 + k] = w1b[i];
    }
    __syncthreads();

    int e = blockIdx.x * 256 + threadIdx.x;   // NE % 256 == 0
    int src, dst;
    load_edge(ei, e, src, dst);

    // Prefetch current dst accumulator values early (latency hides under MLP).
    int* outp = d_h1 + dst * 32;
    int4 cur[8];
    {
        const int4* cp = (const int4*)(const void*)outp;
#pragma unroll
        for (int q = 0; q < 8; q++) cur[q] = cp[q];
    }

    float2 pj = __ldg((const float2*)pos + src);
    float2 pi = __ldg((const float2*)pos + dst);
    float xs[4];
    xs[0] = pj.x; xs[1] = pj.y; xs[2] = pj.x - pi.x; xs[3] = pj.y - pi.y;

    // hidden = relu(x @ w1a + b1a), packed across output pairs
    unsigned long long acc[16];
    {
        const ulonglong2* bp = (const ulonglong2*)s_ba;
#pragma unroll
        for (int q = 0; q < 8; q++) { ulonglong2 b2 = bp[q]; acc[2*q] = b2.x; acc[2*q+1] = b2.y; }
    }
#pragma unroll
    for (int j = 0; j < 4; j++) {
        unsigned long long xd = dup2(xs[j]);
        const ulonglong2* wp = (const ulonglong2*)&s_wa[j * 32];
#pragma unroll
        for (int q = 0; q < 8; q++) {
            ulonglong2 w = wp[q];                      // LDS.128
            acc[2*q]   = fma2(xd, w.x, acc[2*q]);
            acc[2*q+1] = fma2(xd, w.y, acc[2*q+1]);
        }
    }
    unsigned long long hid2[16];
#pragma unroll
    for (int k2 = 0; k2 < 16; k2++) {
        float lo, hi; unpack2(acc[k2], lo, hi);
        hid2[k2] = pack2(fmaxf(lo, 0.0f), fmaxf(hi, 0.0f));
    }

    // m = hidden @ w1b + b1b; conditional atomic seg-max into d_h1[dst]
    const int* curw = (const int*)cur;
#pragma unroll
    for (int c = 0; c < 32; c++) {
        unsigned long long a2 = 0ull;
        const ulonglong2* wr = (const ulonglong2*)&s_wbT[c * 32];
#pragma unroll
        for (int q = 0; q < 8; q++) {
            ulonglong2 w = wr[q];                      // LDS.128
            a2 = fma2(hid2[2*q],   w.x, a2);
            a2 = fma2(hid2[2*q+1], w.y, a2);
        }
        float lo, hi; unpack2(a2, lo, hi);
        float v = lo + hi + s_bb[c];
        // cur >= 0 always; monotone max => stale read is safe to compare against
        if (v > __int_as_float(curw[c]))
            atomicMax(&outp[c], __float_as_int(v));
    }
}

// ---------------- layer 2: [h1(32), dpos(2)] -> 32 -> 32, seg-max into d_h2 ----------------
__global__ void __launch_bounds__(256) layer2_kernel(
    const float* __restrict__ pos,
    const float* __restrict__ w2a, const float* __restrict__ b2a,
    const float* __restrict__ w2b, const float* __restrict__ b2b,
    const void* __restrict__ ei)
{
    __shared__ __align__(16) float s_wa[34 * 32];
    __shared__ __align__(16) float s_ba[32];
    __shared__ __align__(16) float s_wbT[32 * 32];
    __shared__ __align__(16) float s_bb[32];

    for (int i = threadIdx.x; i < 34 * 32; i += 256) s_wa[i] = w2a[i];
    if (threadIdx.x < 32) { s_ba[threadIdx.x] = b2a[threadIdx.x]; s_bb[threadIdx.x] = b2b[threadIdx.x]; }
    for (int i = threadIdx.x; i < 1024; i += 256) {
        int k = i >> 5, c = i & 31;
        s_wbT[c * 32 + k] = w2b[i];
    }
    __syncthreads();

    int e = blockIdx.x * 256 + threadIdx.x;
    int src, dst;
    load_edge(ei, e, src, dst);

    // Prefetch current dst accumulator values early.
    int* outp = d_h2 + dst * 32;
    int4 cur[8];
    {
        const int4* cp = (const int4*)(const void*)outp;
#pragma unroll
        for (int q = 0; q < 8; q++) cur[q] = cp[q];
    }

    float2 pj = __ldg((const float2*)pos + src);
    float2 pi = __ldg((const float2*)pos + dst);

    float xs[34];
    const float4* hp = (const float4*)(const void*)(d_h1 + src * 32);
#pragma unroll
    for (int q = 0; q < 8; q++) {
        float4 v = hp[q];
        xs[4 * q + 0] = v.x; xs[4 * q + 1] = v.y;
        xs[4 * q + 2] = v.z; xs[4 * q + 3] = v.w;
    }
    xs[32] = pj.x - pi.x;
    xs[33] = pj.y - pi.y;

    unsigned long long acc[16];
    {
        const ulonglong2* bp = (const ulonglong2*)s_ba;
#pragma unroll
        for (int q = 0; q < 8; q++) { ulonglong2 b2 = bp[q]; acc[2*q] = b2.x; acc[2*q+1] = b2.y; }
    }
#pragma unroll
    for (int j = 0; j < 34; j++) {
        unsigned long long xd = dup2(xs[j]);
        const ulonglong2* wp = (const ulonglong2*)&s_wa[j * 32];
#pragma unroll
        for (int q = 0; q < 8; q++) {
            ulonglong2 w = wp[q];                      // LDS.128
            acc[2*q]   = fma2(xd, w.x, acc[2*q]);
            acc[2*q+1] = fma2(xd, w.y, acc[2*q+1]);
        }
    }
    unsigned long long hid2[16];
#pragma unroll
    for (int k2 = 0; k2 < 16; k2++) {
        float lo, hi; unpack2(acc[k2], lo, hi);
        hid2[k2] = pack2(fmaxf(lo, 0.0f), fmaxf(hi, 0.0f));
    }

    const int* curw = (const int*)cur;
#pragma unroll
    for (int c = 0; c < 32; c++) {
        unsigned long long a2 = 0ull;
        const ulonglong2* wr = (const ulonglong2*)&s_wbT[c * 32];
#pragma unroll
        for (int q = 0; q < 8; q++) {
            ulonglong2 w = wr[q];                      // LDS.128
            a2 = fma2(hid2[2*q],   w.x, a2);
            a2 = fma2(hid2[2*q+1], w.y, a2);
        }
        float lo, hi; unpack2(a2, lo, hi);
        float v = lo + hi + s_bb[c];
        if (v > __int_as_float(curw[c]))
            atomicMax(&outp[c], __float_as_int(v));
    }
}

// ---------------- global max pool per graph (batch is sorted) ----------------
#define RLEN 128
#define NRANGES ((NN + RLEN - 1) / RLEN)   // 782
#define POOL_THREADS (NRANGES * 32)        // 25024

__global__ void pool_kernel(const void* __restrict__ batch) {
    int t = blockIdx.x * blockDim.x + threadIdx.x;
    if (t >= POOL_THREADS) return;
    int r = t >> 5;        // node range (warp-uniform)
    int c = t & 31;        // channel (lane)
    int n0 = r * RLEN;
    int n1 = min(n0 + RLEN, NN);

    int curg = load_batch(batch, n0);
    float curm = 0.0f;
    for (int n = n0; n < n1; n++) {
        int b = load_batch(batch, n);
        float v = __int_as_float(d_h2[n * 32 + c]);   // >= 0
        if (b != curg) {
            if (curm > 0.0f) atomicMax(&d_pool[curg * 32 + c], __float_as_int(curm));
            curg = b;
            curm = v;
        } else {
            curm = fmaxf(curm, v);
        }
    }
    if (curm > 0.0f) atomicMax(&d_pool[curg * 32 + c], __float_as_int(curm));
}

// ---------------- classifier: out[g] = pool[g] @ wc + bc ----------------
__global__ void final_kernel(const float* __restrict__ wc,
                             const float* __restrict__ bc,
                             float* __restrict__ out) {
    int t = threadIdx.x;
    if (t >= NG * 3) return;
    int g = t / 3, o = t % 3;
    float acc = bc[o];
#pragma unroll
    for (int cc = 0; cc < 32; cc++)
        acc += __int_as_float(d_pool[g * 32 + cc]) * wc[cc * 3 + o];
    out[t] = acc;
}

// ---------------- launch ----------------
extern "C" void kernel_launch(void* const* d_in, const int* in_sizes, int n_in,
                              void* d_out, int out_size) {
    const float* pos = (const float*)d_in[0];
    const float* w1a = (const float*)d_in[1];
    const float* b1a = (const float*)d_in[2];
    const float* w1b = (const float*)d_in[3];
    const float* b1b = (const float*)d_in[4];
    const float* w2a = (const float*)d_in[5];
    const float* b2a = (const float*)d_in[6];
    const float* w2b = (const float*)d_in[7];
    const float* b2b = (const float*)d_in[8];
    const float* wc  = (const float*)d_in[9];
    const float* bc  = (const float*)d_in[10];
    const void* ei    = d_in[11];
    const void* batch = d_in[12];

    detect_kernel<<<1, 32>>>((const int*)ei);
    zero_kernel<<<(NN * 32 + 255) / 256, 256>>>();
    layer1_kernel<<<NE / 256, 256>>>(pos, w1a, b1a, w1b, b1b, ei);
    layer2_kernel<<<NE / 256, 256>>>(pos, w2a, b2a, w2b, b2b, ei);
    pool_kernel<<<(POOL_THREADS + 255) / 256, 256>>>(batch);
    final_kernel<<<1, 192>>>(wc, bc, (float*)d_out);
}

// round 12
// speedup vs baseline: 1.0262x; 1.0005x over previous
#include <cuda_runtime.h>
#include <cstdint>

#define NN 100000
#define NE 3200000
#define NG 64

// Scratch (device globals). Values stored as int bit-patterns of nonnegative
// floats so signed-int atomicMax == float max (0 == 0.0f == identity of
// seg_max0+relu).
__device__ int d_h1[NN * 32];
__device__ int d_h2[NN * 32];
__device__ int d_pool[NG * 32];
__device__ int g_is64;   // 1 if index buffers are int64, 0 if int32

// ---------------- packed f32x2 helpers (sm_100+ PTX) ----------------
__device__ __forceinline__ unsigned long long dup2(float x) {
    unsigned long long r;
    asm("mov.b64 %0, {%1, %1};" : "=l"(r) : "f"(x));
    return r;
}
__device__ __forceinline__ unsigned long long pack2(float lo, float hi) {
    unsigned long long r;
    asm("mov.b64 %0, {%1, %2};" : "=l"(r) : "f"(lo), "f"(hi));
    return r;
}
__device__ __forceinline__ void unpack2(unsigned long long v, float& lo, float& hi) {
    asm("mov.b64 {%0, %1}, %2;" : "=f"(lo), "=f"(hi) : "l"(v));
}
__device__ __forceinline__ unsigned long long fma2(
    unsigned long long a, unsigned long long b, unsigned long long c) {
    unsigned long long d;
    asm("fma.rn.f32x2 %0, %1, %2, %3;" : "=l"(d) : "l"(a), "l"(b), "l"(c));
    return d;
}

// Uniform-branch index fetch honoring detected dtype.
__device__ __forceinline__ void load_edge(const void* ei, int e, int& src, int& dst) {
    if (g_is64) {
        const long long* p = (const long long*)ei;
        src = (int)p[e];
        dst = (int)p[NE + e];
    } else {
        const int* p = (const int*)ei;
        src = p[e];
        dst = p[NE + e];
    }
}
__device__ __forceinline__ int load_batch(const void* b, int n) {
    if (g_is64) return (int)((const long long*)b)[n];
    return ((const int*)b)[n];
}

// ---------------- dtype probe ----------------
// int64 buffer of values in [0, 1e5) viewed as int32: odd words are all 0.
__global__ void detect_kernel(const int* __restrict__ ei32) {
    if (threadIdx.x == 0 && blockIdx.x == 0) {
        int all0 = 1;
#pragma unroll
        for (int i = 1; i < 64; i += 2)
            if (ei32[i] != 0) all0 = 0;
        g_is64 = all0;
    }
}

// ---------------- zero-init ----------------
__global__ void zero_kernel() {
    int i = blockIdx.x * blockDim.x + threadIdx.x;
    if (i < NN * 32) { d_h1[i] = 0; d_h2[i] = 0; }
    if (i < NG * 32) d_pool[i] = 0;
}

// ---------------- layer 1: pos(4) -> 32 -> 32, seg-max into d_h1 ----------------
__global__ void __launch_bounds__(256) layer1_kernel(
    const float* __restrict__ pos,
    const float* __restrict__ w1a, const float* __restrict__ b1a,
    const float* __restrict__ w1b, const float* __restrict__ b1b,
    const void* __restrict__ ei)
{
    __shared__ __align__(16) float s_wa[4 * 32];   // [j][k] (k-pairs contiguous)
    __shared__ __align__(16) float s_ba[32];
    __shared__ __align__(16) float s_wbT[32 * 32]; // transposed: [c][k]
    __shared__ __align__(16) float s_bb[32];

    for (int i = threadIdx.x; i < 128; i += 256) s_wa[i] = w1a[i];
    if (threadIdx.x < 32) { s_ba[threadIdx.x] = b1a[threadIdx.x]; s_bb[threadIdx.x] = b1b[threadIdx.x]; }
    for (int i = threadIdx.x; i < 1024; i += 256) {
        int k = i >> 5, c = i & 31;
        s_wbT[c * 32 + k] = w1b[i];
    }
    __syncthreads();

    int e = blockIdx.x * 256 + threadIdx.x;   // NE % 256 == 0
    int src, dst;
    load_edge(ei, e, src, dst);

    // Prefetch current dst accumulator values early (latency hides under MLP).
    int* outp = d_h1 + dst * 32;
    int4 cur[8];
    {
        const int4* cp = (const int4*)(const void*)outp;
#pragma unroll
        for (int q = 0; q < 8; q++) cur[q] = cp[q];
    }

    float2 pj = __ldg((const float2*)pos + src);
    float2 pi = __ldg((const float2*)pos + dst);
    float xs[4];
    xs[0] = pj.x; xs[1] = pj.y; xs[2] = pj.x - pi.x; xs[3] = pj.y - pi.y;

    // hidden = relu(x @ w1a + b1a), packed across output pairs
    unsigned long long acc[16];
    {
        const ulonglong2* bp = (const ulonglong2*)s_ba;
#pragma unroll
        for (int q = 0; q < 8; q++) { ulonglong2 b2 = bp[q]; acc[2*q] = b2.x; acc[2*q+1] = b2.y; }
    }
#pragma unroll
    for (int j = 0; j < 4; j++) {
        unsigned long long xd = dup2(xs[j]);
        const ulonglong2* wp = (const ulonglong2*)&s_wa[j * 32];
#pragma unroll
        for (int q = 0; q < 8; q++) {
            ulonglong2 w = wp[q];                      // LDS.128
            acc[2*q]   = fma2(xd, w.x, acc[2*q]);
            acc[2*q+1] = fma2(xd, w.y, acc[2*q+1]);
        }
    }
    unsigned long long hid2[16];
#pragma unroll
    for (int k2 = 0; k2 < 16; k2++) {
        float lo, hi; unpack2(acc[k2], lo, hi);
        hid2[k2] = pack2(fmaxf(lo, 0.0f), fmaxf(hi, 0.0f));
    }

    // m = hidden @ w1b + b1b; conditional atomic seg-max into d_h1[dst]
    const int* curw = (const int*)cur;
#pragma unroll
    for (int c = 0; c < 32; c++) {
        unsigned long long a2 = 0ull;
        const ulonglong2* wr = (const ulonglong2*)&s_wbT[c * 32];
#pragma unroll
        for (int q = 0; q < 8; q++) {
            ulonglong2 w = wr[q];                      // LDS.128
            a2 = fma2(hid2[2*q],   w.x, a2);
            a2 = fma2(hid2[2*q+1], w.y, a2);
        }
        float lo, hi; unpack2(a2, lo, hi);
        float v = lo + hi + s_bb[c];
        // cur >= 0 always; monotone max => stale read is safe to compare against
        if (v > __int_as_float(curw[c]))
            atomicMax(&outp[c], __float_as_int(v));
    }
}

// ---------------- layer 2: [h1(32), dpos(2)] -> 32 -> 32, seg-max into d_h2 ----------------
__global__ void __launch_bounds__(256) layer2_kernel(
    const float* __restrict__ pos,
    const float* __restrict__ w2a, const float* __restrict__ b2a,
    const float* __restrict__ w2b, const float* __restrict__ b2b,
    const void* __restrict__ ei)
{
    __shared__ __align__(16) float s_wa[34 * 32];
    __shared__ __align__(16) float s_ba[32];
    __shared__ __align__(16) float s_wbT[32 * 32];
    __shared__ __align__(16) float s_bb[32];

    for (int i = threadIdx.x; i < 34 * 32; i += 256) s_wa[i] = w2a[i];
    if (threadIdx.x < 32) { s_ba[threadIdx.x] = b2a[threadIdx.x]; s_bb[threadIdx.x] = b2b[threadIdx.x]; }
    for (int i = threadIdx.x; i < 1024; i += 256) {
        int k = i >> 5, c = i & 31;
        s_wbT[c * 32 + k] = w2b[i];
    }
    __syncthreads();

    int e = blockIdx.x * 256 + threadIdx.x;
    int src, dst;
    load_edge(ei, e, src, dst);

    // Prefetch current dst accumulator values early.
    int* outp = d_h2 + dst * 32;
    int4 cur[8];
    {
        const int4* cp = (const int4*)(const void*)outp;
#pragma unroll
        for (int q = 0; q < 8; q++) cur[q] = cp[q];
    }

    float2 pj = __ldg((const float2*)pos + src);
    float2 pi = __ldg((const float2*)pos + dst);

    float xs[34];
    const float4* hp = (const float4*)(const void*)(d_h1 + src * 32);
#pragma unroll
    for (int q = 0; q < 8; q++) {
        float4 v = hp[q];
        xs[4 * q + 0] = v.x; xs[4 * q + 1] = v.y;
        xs[4 * q + 2] = v.z; xs[4 * q + 3] = v.w;
    }
    xs[32] = pj.x - pi.x;
    xs[33] = pj.y - pi.y;

    unsigned long long acc[16];
    {
        const ulonglong2* bp = (const ulonglong2*)s_ba;
#pragma unroll
        for (int q = 0; q < 8; q++) { ulonglong2 b2 = bp[q]; acc[2*q] = b2.x; acc[2*q+1] = b2.y; }
    }
#pragma unroll
    for (int j = 0; j < 34; j++) {
        unsigned long long xd = dup2(xs[j]);
        const ulonglong2* wp = (const ulonglong2*)&s_wa[j * 32];
#pragma unroll
        for (int q = 0; q < 8; q++) {
            ulonglong2 w = wp[q];                      // LDS.128
            acc[2*q]   = fma2(xd, w.x, acc[2*q]);
            acc[2*q+1] = fma2(xd, w.y, acc[2*q+1]);
        }
    }
    unsigned long long hid2[16];
#pragma unroll
    for (int k2 = 0; k2 < 16; k2++) {
        float lo, hi; unpack2(acc[k2], lo, hi);
        hid2[k2] = pack2(fmaxf(lo, 0.0f), fmaxf(hi, 0.0f));
    }

    const int* curw = (const int*)cur;
#pragma unroll
    for (int c = 0; c < 32; c++) {
        unsigned long long a2 = 0ull;
        const ulonglong2* wr = (const ulonglong2*)&s_wbT[c * 32];
#pragma unroll
        for (int q = 0; q < 8; q++) {
            ulonglong2 w = wr[q];                      // LDS.128
            a2 = fma2(hid2[2*q],   w.x, a2);
            a2 = fma2(hid2[2*q+1], w.y, a2);
        }
        float lo, hi; unpack2(a2, lo, hi);
        float v = lo + hi + s_bb[c];
        if (v > __int_as_float(curw[c]))
            atomicMax(&outp[c], __float_as_int(v));
    }
}

// ---------------- global max pool per graph (batch is sorted) ----------------
#define RLEN 128
#define NRANGES ((NN + RLEN - 1) / RLEN)   // 782
#define POOL_THREADS (NRANGES * 32)        // 25024

__global__ void pool_kernel(const void* __restrict__ batch) {
    int t = blockIdx.x * blockDim.x + threadIdx.x;
    if (t >= POOL_THREADS) return;
    int r = t >> 5;        // node range (warp-uniform)
    int c = t & 31;        // channel (lane)
    int n0 = r * RLEN;
    int n1 = min(n0 + RLEN, NN);

    int curg = load_batch(batch, n0);
    float curm = 0.0f;
    for (int n = n0; n < n1; n++) {
        int b = load_batch(batch, n);
        float v = __int_as_float(d_h2[n * 32 + c]);   // >= 0
        if (b != curg) {
            if (curm > 0.0f) atomicMax(&d_pool[curg * 32 + c], __float_as_int(curm));
            curg = b;
            curm = v;
        } else {
            curm = fmaxf(curm, v);
        }
    }
    if (curm > 0.0f) atomicMax(&d_pool[curg * 32 + c], __float_as_int(curm));
}

// ---------------- classifier: out[g] = pool[g] @ wc + bc ----------------
__global__ void final_kernel(const float* __restrict__ wc,
                             const float* __restrict__ bc,
                             float* __restrict__ out) {
    int t = threadIdx.x;
    if (t >= NG * 3) return;
    int g = t / 3, o = t % 3;
    float acc = bc[o];
#pragma unroll
    for (int cc = 0; cc < 32; cc++)
        acc += __int_as_float(d_pool[g * 32 + cc]) * wc[cc * 3 + o];
    out[t] = acc;
}

// ---------------- launch ----------------
extern "C" void kernel_launch(void* const* d_in, const int* in_sizes, int n_in,
                              void* d_out, int out_size) {
    const float* pos = (const float*)d_in[0];
    const float* w1a = (const float*)d_in[1];
    const float* b1a = (const float*)d_in[2];
    const float* w1b = (const float*)d_in[3];
    const float* b1b = (const float*)d_in[4];
    const float* w2a = (const float*)d_in[5];
    const float* b2a = (const float*)d_in[6];
    const float* w2b = (const float*)d_in[7];
    const float* b2b = (const float*)d_in[8];
    const float* wc  = (const float*)d_in[9];
    const float* bc  = (const float*)d_in[10];
    const void* ei    = d_in[11];
    const void* batch = d_in[12];

    detect_kernel<<<1, 32>>>((const int*)ei);
    zero_kernel<<<(NN * 32 + 255) / 256, 256>>>();
    layer1_kernel<<<NE / 256, 256>>>(pos, w1a, b1a, w1b, b1b, ei);
    layer2_kernel<<<NE / 256, 256>>>(pos, w2a, b2a, w2b, b2b, ei);
    pool_kernel<<<(POOL_THREADS + 255) / 256, 256>>>(batch);
    final_kernel<<<1, 192>>>(wc, bc, (float*)d_out);
}